// round 8
// baseline (speedup 1.0000x reference)
#include <cuda_runtime.h>
#include <cuda_fp16.h>
#include <math.h>

#define N_IN   128
#define NLAY   6
#define N_H    320
#define DEG    32
#define N_OUT  18
#define BATCH  8192
#define BT     64              // batch rows per CTA (2 per lane via half2)
#define PAIRS  32              // row-pairs per tile == lanes
#define SMEM_NODES 1680        // nodes resident in shared (rest -> scratch)
#define SCR_NODES  (2048 - SMEM_NODES)   // 368
#define NTILES (BATCH / BT)    // 128 CTAs, single wave
#define NWARPS 32
#define NTHREADS (NWARPS * 32) // 1024
#define GSZ    32              // neurons per group (== NWARPS)
#define GPL    (N_H / GSZ)     // 10 groups per layer
#define NGROUPS (NLAY * GPL)   // 60
#define SWORDS (GSZ * DEG)     // 1024 stage words (1 per thread)
#define HWORDS (N_OUT * DEG)   // 576 head stage words

// Spilled activations (nodes [1680,2048)); guarded gathers read them back.
__device__ __half2 g_scratch[(size_t)NTILES * SCR_NODES * PAIRS];

struct SMem {
    __half2 acts[SMEM_NODES * PAIRS];  // 215,040 B node-major, pair = lane
    int     sidx[2][SWORDS];           //   8,192 B double-buffered idx stage
    __half2 sw  [2][SWORDS];           //   8,192 B double-buffered (w,w) stage
};                                      // 231,424 B total (cap 232,448)
// NOTE: stage is warp-PRIVATE: thread w*32+lane writes word w*32+lane, and
// warp w reads exactly words [w*32, w*32+32). No cross-warp stage sync needed.

__device__ __forceinline__ float fast_tanh(float x) {
    float y;
    asm("tanh.approx.f32 %0, %1;" : "=f"(y) : "f"(x));
    return y;
}

// One group's neuron compute: warp = one neuron x 64 batch rows.
// GUARD=true adds the scratch fallback for indices >= SMEM_NODES (layer 5 only).
template<bool GUARD>
__device__ __forceinline__ void group_compute(
    const int* __restrict__ sidx, const __half2* __restrict__ sw,
    const __half2* __restrict__ sa, const __half2* __restrict__ scr,
    __half2* __restrict__ sa_mut, __half2* __restrict__ scr_mut,
    const float* __restrict__ hid_b, int m, int warp)
{
    const int4*  ip = (const int4*) (sidx + warp * DEG);  // LDS.128 (own words)
    const uint4* wp = (const uint4*)(sw   + warp * DEG);
    __half2 acc[8];
    #pragma unroll
    for (int k = 0; k < 8; k++) acc[k] = __floats2half2_rn(0.f, 0.f);
    #pragma unroll
    for (int c = 0; c < DEG / 4; c++) {
        const int4  i4 = ip[c];
        const uint4 w4 = wp[c];
        const int k = (c & 1) * 4;     // 8 chains x 4 terms (R5 numerics)
        #define GLOAD(II) (GUARD ? (((II) < SMEM_NODES) ? sa[(II) * PAIRS]             \
                                     : scr[((II) - SMEM_NODES) * PAIRS])               \
                                 : sa[(II) * PAIRS])
        acc[k + 0] = __hfma2(GLOAD(i4.x), *(const __half2*)&w4.x, acc[k + 0]);
        acc[k + 1] = __hfma2(GLOAD(i4.y), *(const __half2*)&w4.y, acc[k + 1]);
        acc[k + 2] = __hfma2(GLOAD(i4.z), *(const __half2*)&w4.z, acc[k + 2]);
        acc[k + 3] = __hfma2(GLOAD(i4.w), *(const __half2*)&w4.w, acc[k + 3]);
        #undef GLOAD
    }
    const float bb = hid_b[m * GSZ + warp];
    float sl = bb, sh = bb;
    #pragma unroll
    for (int k = 0; k < 8; k++) {
        const float2 f = __half22float2(acc[k]);
        sl += f.x; sh += f.y;
    }
    const __half2 hv = __floats2half2_rn(fast_tanh(sl), fast_tanh(sh));
    const int node = N_IN + m * GSZ + warp;
    if (node < SMEM_NODES) sa_mut [node * PAIRS] = hv;                 // STS
    else                   scr_mut[(node - SMEM_NODES) * PAIRS] = hv;  // STG
}

__global__ void __launch_bounds__(NTHREADS, 1)
policy_kernel(const float* __restrict__ obs,      // [BATCH, N_IN]
              const int*   __restrict__ hid_src,  // [NLAY*N_H*DEG] flat
              const float* __restrict__ hid_w,    // [NLAY*N_H*DEG] flat
              const float* __restrict__ hid_b,    // [NLAY*N_H] flat
              const int*   __restrict__ out_src,  // [N_OUT, DEG]
              const float* __restrict__ out_w,    // [N_OUT, DEG]
              const float* __restrict__ out_b,    // [N_OUT]
              float*       __restrict__ out)      // [BATCH, N_OUT]
{
    extern __shared__ char raw[];
    SMem* s = (SMem*)raw;
    const int tid  = threadIdx.x;
    const int lane = tid & 31;
    const int warp = tid >> 5;
    const int tile = blockIdx.x;

    // ---- obs -> node-major half2 smem. Lane p owns batch rows (2p, 2p+1).
    {
        const int r0 = tile * BT + 2 * lane;
        const float4* o0 = (const float4*)(obs + (size_t)r0 * N_IN);
        const float4* o1 = (const float4*)(obs + (size_t)(r0 + 1) * N_IN);
        const int q = warp;                // 32 warps cover N_IN/4 = 32 quads
        float4 a = o0[q], b = o1[q];
        s->acts[(q * 4 + 0) * PAIRS + lane] = __floats2half2_rn(a.x, b.x);
        s->acts[(q * 4 + 1) * PAIRS + lane] = __floats2half2_rn(a.y, b.y);
        s->acts[(q * 4 + 2) * PAIRS + lane] = __floats2half2_rn(a.z, b.z);
        s->acts[(q * 4 + 3) * PAIRS + lane] = __floats2half2_rn(a.w, b.w);
    }

    const __half2* __restrict__ sa = s->acts + lane;
    __half2* __restrict__ sa_mut   = s->acts + lane;
    __half2* __restrict__ scr_mut  = g_scratch + (size_t)tile * (SCR_NODES * PAIRS) + lane;
    const __half2* __restrict__ scr = scr_mut;

    // ---- Preload stage for group m=0 into buffer 0 (warp-private words).
    s->sidx[0][tid] = hid_src[tid];
    s->sw  [0][tid] = __float2half2_rn(hid_w[tid]);
    __syncthreads();   // obs acts + initial stage visible

    int buf = 0;
    // ---- Layers 0-4: pure-smem gathers. NO block barrier inside a layer:
    // stage is warp-private, and layer l reads only nodes < N_IN + l*N_H.
    for (int l = 0; l < NLAY - 1; l++) {
        #pragma unroll 1
        for (int g = 0; g < GPL; g++) {
            const int m = l * GPL + g;
            // prefetch next group's warp-private words (LDG hidden under compute)
            const int   pidx = hid_src[(m + 1) * SWORDS + tid];
            const float pw   = hid_w [(m + 1) * SWORDS + tid];

            group_compute<false>(s->sidx[buf], s->sw[buf], sa, scr,
                                 sa_mut, scr_mut, hid_b, m, warp);

            s->sidx[buf ^ 1][tid] = pidx;            // own words only
            s->sw  [buf ^ 1][tid] = __float2half2_rn(pw);
            __syncwarp();                            // intra-warp visibility
            buf ^= 1;
        }
        __syncthreads();   // layer boundary: this layer's acts (smem+scratch)
    }
    // ---- Layer 5: gathers may hit scratch; head stage prefetched at the end.
    #pragma unroll 1
    for (int g = 0; g < GPL; g++) {
        const int m = (NLAY - 1) * GPL + g;
        int pidx = 0; float pw = 0.f;
        if (m + 1 < NGROUPS)   { pidx = hid_src[(m + 1) * SWORDS + tid];
                                 pw   = hid_w [(m + 1) * SWORDS + tid]; }
        else if (tid < HWORDS) { pidx = out_src[tid]; pw = out_w[tid]; }

        group_compute<true>(s->sidx[buf], s->sw[buf], sa, scr,
                            sa_mut, scr_mut, hid_b, m, warp);

        if (m + 1 < NGROUPS || tid < HWORDS) {
            s->sidx[buf ^ 1][tid] = pidx;
            s->sw  [buf ^ 1][tid] = __float2half2_rn(pw);
        }
        __syncwarp();
        buf ^= 1;
    }
    __syncthreads();       // layer-5 acts (incl. scratch STG) + head stage

    // ---- output head: 18 neurons (warps 0..17); accurate tanh on outputs.
    if (warp < N_OUT) {
        const int4*  ip = (const int4*) (s->sidx[buf] + warp * DEG);
        const uint4* wp = (const uint4*)(s->sw  [buf] + warp * DEG);
        __half2 acc[8];
        #pragma unroll
        for (int k = 0; k < 8; k++) acc[k] = __floats2half2_rn(0.f, 0.f);
        #pragma unroll
        for (int c = 0; c < DEG / 4; c++) {
            const int4  i4 = ip[c];
            const uint4 w4 = wp[c];
            const int k = (c & 1) * 4;
            #define GATH(II, WW, KK) { const int ii = (II);                           \
                const __half2 v = (ii < SMEM_NODES) ? sa[ii * PAIRS]                  \
                                                    : scr[(ii - SMEM_NODES) * PAIRS]; \
                acc[KK] = __hfma2(v, *(const __half2*)&(WW), acc[KK]); }
            GATH(i4.x, w4.x, k + 0); GATH(i4.y, w4.y, k + 1);
            GATH(i4.z, w4.z, k + 2); GATH(i4.w, w4.w, k + 3);
            #undef GATH
        }
        const float bo = out_b[warp];
        float sl = bo, sh = bo;
        #pragma unroll
        for (int k = 0; k < 8; k++) {
            const float2 f = __half22float2(acc[k]);
            sl += f.x; sh += f.y;
        }
        const int r0 = tile * BT + 2 * lane;
        out[(size_t)r0       * N_OUT + warp] = tanhf(sl);
        out[(size_t)(r0 + 1) * N_OUT + warp] = tanhf(sh);
    }
}

extern "C" void kernel_launch(void* const* d_in, const int* in_sizes, int n_in,
                              void* d_out, int out_size)
{
    const float* obs     = (const float*)d_in[0];
    const int*   hid_src = (const int*)  d_in[1];
    const float* hid_w   = (const float*)d_in[2];
    const float* hid_b   = (const float*)d_in[3];
    const int*   out_src = (const int*)  d_in[4];
    const float* out_w   = (const float*)d_in[5];
    const float* out_b   = (const float*)d_in[6];
    float*       out     = (float*)d_out;

    const size_t smem = sizeof(SMem);  // 231,424 B
    cudaFuncSetAttribute(policy_kernel,
                         cudaFuncAttributeMaxDynamicSharedMemorySize, (int)smem);
    policy_kernel<<<NTILES, NTHREADS, smem>>>(obs, hid_src, hid_w, hid_b,
                                              out_src, out_w, out_b, out);
}

// round 10
// speedup vs baseline: 1.3483x; 1.3483x over previous
#include <cuda_runtime.h>
#include <cuda_fp16.h>
#include <math.h>

#define N_IN   128
#define NLAY   6
#define N_H    320
#define DEG    32
#define N_OUT  18
#define BATCH  8192
#define BT     64              // batch rows per CTA (2 per lane via half2)
#define PAIRS  32              // row-pairs per tile == lanes
#define SMEM_NODES 1680        // nodes resident in shared (rest -> scratch)
#define SCR_NODES  (2048 - SMEM_NODES)   // 368
#define NTILES (BATCH / BT)    // 128 CTAs, single wave
#define NWARPS 32
#define NTHREADS (NWARPS * 32) // 1024
#define GSZ    32              // neurons per group (== NWARPS)
#define NGROUPS (NLAY * N_H / GSZ)   // 60
#define FASTG  50              // groups 0..49 (layers 0-4): sources < 1408 -> pure smem
#define SWORDS (GSZ * DEG)     // 1024 stage words (1 per thread)
#define HWORDS (N_OUT * DEG)   // 576 head stage words

// Spilled activations (nodes [1680,2048)); guarded gathers read them back.
__device__ __half2 g_scratch[(size_t)NTILES * SCR_NODES * PAIRS];

struct SMem {
    __half2 acts[SMEM_NODES * PAIRS];  // 215,040 B node-major, pair = lane
    int     sidx[2][SWORDS];           //   8,192 B double-buffered idx stage
    __half2 sw  [2][SWORDS];           //   8,192 B double-buffered (w,w) stage
};                                      // 231,424 B total (cap 232,448)

__device__ __forceinline__ float fast_tanh(float x) {
    float y;
    asm("tanh.approx.f32 %0, %1;" : "=f"(y) : "f"(x));
    return y;
}

// One group's neuron compute: warp = one neuron x 64 batch rows.
// GUARD=true adds the scratch fallback for indices >= SMEM_NODES (layer 5 only).
template<bool GUARD>
__device__ __forceinline__ void group_compute(
    const int* __restrict__ sidx, const __half2* __restrict__ sw,
    const __half2* __restrict__ sa, const __half2* __restrict__ scr,
    __half2* __restrict__ sa_mut, __half2* __restrict__ scr_mut,
    const float* __restrict__ hid_b, int m, int warp)
{
    const int4*  ip = (const int4*) (sidx + warp * DEG);  // LDS.128 (own words)
    const uint4* wp = (const uint4*)(sw   + warp * DEG);
    __half2 acc[8];
    #pragma unroll
    for (int k = 0; k < 8; k++) acc[k] = __floats2half2_rn(0.f, 0.f);
    #pragma unroll
    for (int c = 0; c < DEG / 4; c++) {
        const int4  i4 = ip[c];
        const uint4 w4 = wp[c];
        const int k = (c & 1) * 4;     // 8 chains x 4 terms (R5/R7 numerics)
        #define GLOAD(II) (GUARD ? (((II) < SMEM_NODES) ? sa[(II) * PAIRS]             \
                                     : scr[((II) - SMEM_NODES) * PAIRS])               \
                                 : sa[(II) * PAIRS])
        acc[k + 0] = __hfma2(GLOAD(i4.x), *(const __half2*)&w4.x, acc[k + 0]);
        acc[k + 1] = __hfma2(GLOAD(i4.y), *(const __half2*)&w4.y, acc[k + 1]);
        acc[k + 2] = __hfma2(GLOAD(i4.z), *(const __half2*)&w4.z, acc[k + 2]);
        acc[k + 3] = __hfma2(GLOAD(i4.w), *(const __half2*)&w4.w, acc[k + 3]);
        #undef GLOAD
    }
    // Epilogue: one fp16 pair-reduction level (4 HADD2), then fp32 finish.
    const __half2 r0 = __hadd2(acc[0], acc[1]);
    const __half2 r1 = __hadd2(acc[2], acc[3]);
    const __half2 r2 = __hadd2(acc[4], acc[5]);
    const __half2 r3 = __hadd2(acc[6], acc[7]);
    const float2 f0 = __half22float2(r0);
    const float2 f1 = __half22float2(r1);
    const float2 f2 = __half22float2(r2);
    const float2 f3 = __half22float2(r3);
    const float bb = hid_b[m * GSZ + warp];
    const float sl = ((f0.x + f1.x) + (f2.x + f3.x)) + bb;
    const float sh = ((f0.y + f1.y) + (f2.y + f3.y)) + bb;
    const __half2 hv = __floats2half2_rn(fast_tanh(sl), fast_tanh(sh));
    const int node = N_IN + m * GSZ + warp;
    if (node < SMEM_NODES) sa_mut [node * PAIRS] = hv;                 // STS
    else                   scr_mut[(node - SMEM_NODES) * PAIRS] = hv;  // STG
}

__global__ void __launch_bounds__(NTHREADS, 1)
policy_kernel(const float* __restrict__ obs,      // [BATCH, N_IN]
              const int*   __restrict__ hid_src,  // [NLAY*N_H*DEG] flat
              const float* __restrict__ hid_w,    // [NLAY*N_H*DEG] flat
              const float* __restrict__ hid_b,    // [NLAY*N_H] flat
              const int*   __restrict__ out_src,  // [N_OUT, DEG]
              const float* __restrict__ out_w,    // [N_OUT, DEG]
              const float* __restrict__ out_b,    // [N_OUT]
              float*       __restrict__ out)      // [BATCH, N_OUT]
{
    extern __shared__ char raw[];
    SMem* s = (SMem*)raw;
    const int tid  = threadIdx.x;
    const int lane = tid & 31;
    const int warp = tid >> 5;
    const int tile = blockIdx.x;

    // ---- obs -> node-major half2 smem. Lane p owns batch rows (2p, 2p+1).
    {
        const int r0 = tile * BT + 2 * lane;
        const float4* o0 = (const float4*)(obs + (size_t)r0 * N_IN);
        const float4* o1 = (const float4*)(obs + (size_t)(r0 + 1) * N_IN);
        const int q = warp;                // 32 warps cover N_IN/4 = 32 quads
        float4 a = o0[q], b = o1[q];
        s->acts[(q * 4 + 0) * PAIRS + lane] = __floats2half2_rn(a.x, b.x);
        s->acts[(q * 4 + 1) * PAIRS + lane] = __floats2half2_rn(a.y, b.y);
        s->acts[(q * 4 + 2) * PAIRS + lane] = __floats2half2_rn(a.z, b.z);
        s->acts[(q * 4 + 3) * PAIRS + lane] = __floats2half2_rn(a.w, b.w);
    }

    const __half2* __restrict__ sa = s->acts + lane;
    __half2* __restrict__ sa_mut   = s->acts + lane;
    __half2* __restrict__ scr_mut  = g_scratch + (size_t)tile * (SCR_NODES * PAIRS) + lane;
    const __half2* __restrict__ scr = scr_mut;

    // ---- Preload stage for group m=0 into buffer 0.
    s->sidx[0][tid] = hid_src[tid];
    s->sw  [0][tid] = __float2half2_rn(hid_w[tid]);
    __syncthreads();   // obs acts + initial stage visible

    int buf = 0;
    // ---- Fast groups (layers 0-4): pure-smem gathers.
    for (int m = 0; m < FASTG; m++) {
        // prefetch next stage (LDG at top: latency hidden under compute)
        const int   pidx = hid_src[(m + 1) * SWORDS + tid];
        const float pw   = hid_w [(m + 1) * SWORDS + tid];

        group_compute<false>(s->sidx[buf], s->sw[buf], sa, scr, sa_mut, scr_mut,
                             hid_b, m, warp);

        s->sidx[buf ^ 1][tid] = pidx;           // STS after compute
        s->sw  [buf ^ 1][tid] = __float2half2_rn(pw);
        __syncthreads();                        // single barrier per group
        buf ^= 1;
    }
    // ---- Guarded groups (layer 5): gathers may hit scratch.
    for (int m = FASTG; m < NGROUPS; m++) {
        int pidx = 0; float pw = 0.f;
        const bool have = (m + 1 < NGROUPS) || (tid < HWORDS);
        if (m + 1 < NGROUPS)   { pidx = hid_src[(m + 1) * SWORDS + tid];
                                 pw   = hid_w [(m + 1) * SWORDS + tid]; }
        else if (tid < HWORDS) { pidx = out_src[tid]; pw = out_w[tid]; }

        group_compute<true>(s->sidx[buf], s->sw[buf], sa, scr, sa_mut, scr_mut,
                            hid_b, m, warp);

        if (have) {
            s->sidx[buf ^ 1][tid] = pidx;
            s->sw  [buf ^ 1][tid] = __float2half2_rn(pw);
        }
        __syncthreads();
        buf ^= 1;
    }

    // ---- output head: 18 neurons (warps 0..17); accurate tanh on outputs.
    if (warp < N_OUT) {
        const int4*  ip = (const int4*) (s->sidx[buf] + warp * DEG);
        const uint4* wp = (const uint4*)(s->sw  [buf] + warp * DEG);
        __half2 acc[8];
        #pragma unroll
        for (int k = 0; k < 8; k++) acc[k] = __floats2half2_rn(0.f, 0.f);
        #pragma unroll
        for (int c = 0; c < DEG / 4; c++) {
            const int4  i4 = ip[c];
            const uint4 w4 = wp[c];
            const int k = (c & 1) * 4;
            #define GATH(II, WW, KK) { const int ii = (II);                           \
                const __half2 v = (ii < SMEM_NODES) ? sa[ii * PAIRS]                  \
                                                    : scr[(ii - SMEM_NODES) * PAIRS]; \
                acc[KK] = __hfma2(v, *(const __half2*)&(WW), acc[KK]); }
            GATH(i4.x, w4.x, k + 0); GATH(i4.y, w4.y, k + 1);
            GATH(i4.z, w4.z, k + 2); GATH(i4.w, w4.w, k + 3);
            #undef GATH
        }
        const __half2 r0h = __hadd2(acc[0], acc[1]);
        const __half2 r1h = __hadd2(acc[2], acc[3]);
        const __half2 r2h = __hadd2(acc[4], acc[5]);
        const __half2 r3h = __hadd2(acc[6], acc[7]);
        const float2 f0 = __half22float2(r0h);
        const float2 f1 = __half22float2(r1h);
        const float2 f2 = __half22float2(r2h);
        const float2 f3 = __half22float2(r3h);
        const float bo = out_b[warp];
        const float sl = ((f0.x + f1.x) + (f2.x + f3.x)) + bo;
        const float sh = ((f0.y + f1.y) + (f2.y + f3.y)) + bo;
        const int r0 = tile * BT + 2 * lane;
        out[(size_t)r0       * N_OUT + warp] = tanhf(sl);
        out[(size_t)(r0 + 1) * N_OUT + warp] = tanhf(sh);
    }
}

extern "C" void kernel_launch(void* const* d_in, const int* in_sizes, int n_in,
                              void* d_out, int out_size)
{
    const float* obs     = (const float*)d_in[0];
    const int*   hid_src = (const int*)  d_in[1];
    const float* hid_w   = (const float*)d_in[2];
    const float* hid_b   = (const float*)d_in[3];
    const int*   out_src = (const int*)  d_in[4];
    const float* out_w   = (const float*)d_in[5];
    const float* out_b   = (const float*)d_in[6];
    float*       out     = (float*)d_out;

    const size_t smem = sizeof(SMem);  // 231,424 B
    cudaFuncSetAttribute(policy_kernel,
                         cudaFuncAttributeMaxDynamicSharedMemorySize, (int)smem);
    policy_kernel<<<NTILES, NTHREADS, smem>>>(obs, hid_src, hid_w, hid_b,
                                              out_src, out_w, out_b, out);
}

// round 14
// speedup vs baseline: 1.3998x; 1.0382x over previous
#include <cuda_runtime.h>
#include <cuda_fp16.h>
#include <stdint.h>
#include <math.h>

#define N_IN   128
#define NLAY   6
#define N_H    320
#define DEG    32
#define N_OUT  18
#define BATCH  8192
#define BT     64              // batch rows per CTA (2 per lane via half2)
#define PAIRS  32              // row-pairs per tile == lanes
#define SMEM_NODES 1552        // nodes resident in shared (rest -> scratch)
#define SCR_NODES  (2048 - SMEM_NODES)   // 496
#define NTILES (BATCH / BT)    // 128 CTAs, single wave
#define NWARPS 32
#define NTHREADS (NWARPS * 32) // 1024
#define GSZ    64              // neurons per group (2 per warp, sequential)
#define NGROUPS (NLAY * N_H / GSZ)   // 30
#define FASTG  25              // groups 0..24 (layers 0-4): sources < 1408 -> pure smem
#define SWORDS (GSZ * DEG)     // 2048 packed (idx,w) entries per group
#define HWORDS (N_OUT * DEG)   // 576 head entries
#define PACK_N (NLAY * N_H * DEG + HWORDS)   // 62016

// Packed (src_idx, half2(w,w)) pairs, rebuilt by pack_kernel every call.
__device__ __align__(16) int2 g_pack[PACK_N];
// Spilled activations (nodes [1552,2048)); guarded gathers read them back.
__device__ __half2 g_scratch[(size_t)NTILES * SCR_NODES * PAIRS];

struct SMem {
    __half2 acts[SMEM_NODES * PAIRS];  // 198,656 B node-major, pair = lane
    int2    stage[2][SWORDS];          //  32,768 B double-buffered (idx,w) stage
};                                      // 231,424 B total

__device__ __forceinline__ float fast_tanh(float x) {
    float y;
    asm("tanh.approx.f32 %0, %1;" : "=f"(y) : "f"(x));
    return y;
}
__device__ __forceinline__ void cp_async16(unsigned int saddr, const void* g) {
    asm volatile("cp.async.ca.shared.global [%0], [%1], 16;" :: "r"(saddr), "l"(g));
}
__device__ __forceinline__ void cp_async8(unsigned int saddr, const void* g) {
    asm volatile("cp.async.ca.shared.global [%0], [%1], 8;" :: "r"(saddr), "l"(g));
}
#define CP_COMMIT() asm volatile("cp.async.commit_group;" ::: "memory")
#define CP_WAIT0()  asm volatile("cp.async.wait_group 0;"  ::: "memory")

// One neuron: 32 gathers from the packed stage. Chain mapping == R7:
// term d -> acc[((d/4)&1)*4 + d%4]; sequential fp32 epilogue (R7 numerics).
template<bool GUARD>
__device__ __forceinline__ __half2 neuron_compute(
    const int2* __restrict__ stg_n,          // stage + n_local*DEG
    const __half2* __restrict__ sa, const __half2* __restrict__ scr,
    float bb)
{
    const int4* pp = (const int4*)stg_n;     // 16x LDS.128, each = 2 (idx,w) pairs
    __half2 acc[8];
    #pragma unroll
    for (int k = 0; k < 8; k++) acc[k] = __floats2half2_rn(0.f, 0.f);
    #pragma unroll
    for (int c = 0; c < DEG / 2; c++) {      // terms d = 2c, 2c+1
        const int4 p = pp[c];
        const int q  = ((c >> 1) & 1) * 4;
        const int e0 = (2 * c) & 3;          // e0 in {0,2}
        #define GLOAD(II) (GUARD ? (((II) < SMEM_NODES) ? sa[(II) * PAIRS]             \
                                     : scr[((II) - SMEM_NODES) * PAIRS])               \
                                 : sa[(II) * PAIRS])
        acc[q + e0]     = __hfma2(GLOAD(p.x), *(const __half2*)&p.y, acc[q + e0]);
        acc[q + e0 + 1] = __hfma2(GLOAD(p.z), *(const __half2*)&p.w, acc[q + e0 + 1]);
        #undef GLOAD
    }
    float sl = bb, sh = bb;
    #pragma unroll
    for (int k = 0; k < 8; k++) {
        const float2 f = __half22float2(acc[k]);
        sl += f.x; sh += f.y;
    }
    return __floats2half2_rn(fast_tanh(sl), fast_tanh(sh));
}

// Pre-pass: pack (idx, half2(w,w)) for hidden layers + head.
__global__ void pack_kernel(const int* __restrict__ hs, const float* __restrict__ hw,
                            const int* __restrict__ os, const float* __restrict__ ow)
{
    const int i = blockIdx.x * 256 + threadIdx.x;
    if (i >= PACK_N) return;
    int idx; float w;
    if (i < NLAY * N_H * DEG) { idx = hs[i]; w = hw[i]; }
    else { const int j = i - NLAY * N_H * DEG; idx = os[j]; w = ow[j]; }
    const __half2 w2 = __float2half2_rn(w);
    g_pack[i] = make_int2(idx, *(const int*)&w2);
}

__global__ void __launch_bounds__(NTHREADS, 1)
policy_kernel(const float* __restrict__ obs,      // [BATCH, N_IN]
              const float* __restrict__ hid_b,    // [NLAY*N_H] flat
              const float* __restrict__ out_b,    // [N_OUT]
              float*       __restrict__ out)      // [BATCH, N_OUT]
{
    extern __shared__ char raw[];
    SMem* s = (SMem*)raw;
    const int tid  = threadIdx.x;
    const int lane = tid & 31;
    const int warp = tid >> 5;
    const int tile = blockIdx.x;

    // ---- obs -> node-major half2 smem. Lane p owns batch rows (2p, 2p+1).
    {
        const int r0 = tile * BT + 2 * lane;
        const float4* o0 = (const float4*)(obs + (size_t)r0 * N_IN);
        const float4* o1 = (const float4*)(obs + (size_t)(r0 + 1) * N_IN);
        const int q = warp;                // 32 warps cover N_IN/4 = 32 quads
        float4 a = o0[q], b = o1[q];
        s->acts[(q * 4 + 0) * PAIRS + lane] = __floats2half2_rn(a.x, b.x);
        s->acts[(q * 4 + 1) * PAIRS + lane] = __floats2half2_rn(a.y, b.y);
        s->acts[(q * 4 + 2) * PAIRS + lane] = __floats2half2_rn(a.z, b.z);
        s->acts[(q * 4 + 3) * PAIRS + lane] = __floats2half2_rn(a.w, b.w);
    }

    const __half2* __restrict__ sa = s->acts + lane;
    __half2* __restrict__ sa_mut   = s->acts + lane;
    __half2* __restrict__ scr_mut  = g_scratch + (size_t)tile * (SCR_NODES * PAIRS) + lane;
    const __half2* __restrict__ scr = scr_mut;

    const unsigned int st0 = (unsigned int)__cvta_generic_to_shared(&s->stage[0][2 * tid]);
    const unsigned int st1 = (unsigned int)__cvta_generic_to_shared(&s->stage[1][2 * tid]);

    // ---- Preload stage for group m=0 into buffer 0 (16 B per thread).
    cp_async16(st0, g_pack + 2 * tid);
    CP_COMMIT();
    CP_WAIT0();
    __syncthreads();   // obs acts + initial stage visible

    int buf = 0;
    // ---- Fast groups (layers 0-4): pure-smem gathers.
    for (int m = 0; m < FASTG; m++) {
        // async prefetch of next group's packed words (no registers held)
        cp_async16(buf ? st0 : st1, g_pack + (size_t)(m + 1) * SWORDS + 2 * tid);
        CP_COMMIT();

        const int2* stg = s->stage[buf];
        #pragma unroll 1
        for (int h = 0; h < 2; h++) {      // 2 neurons per warp, sequential
            const int nl = h * 32 + warp;  // neuron-in-group
            const __half2 hv = neuron_compute<false>(
                stg + nl * DEG, sa, scr, hid_b[m * GSZ + nl]);
            const int node = N_IN + m * GSZ + nl;
            if (node < SMEM_NODES) sa_mut [node * PAIRS] = hv;
            else                   scr_mut[(node - SMEM_NODES) * PAIRS] = hv;
        }

        CP_WAIT0();
        __syncthreads();                   // one barrier per 64 neurons
        buf ^= 1;
    }
    // ---- Guarded groups (layer 5): gathers may hit scratch.
    for (int m = FASTG; m < NGROUPS; m++) {
        if (m + 1 < NGROUPS)
            cp_async16(buf ? st0 : st1, g_pack + (size_t)(m + 1) * SWORDS + 2 * tid);
        CP_COMMIT();

        const int2* stg = s->stage[buf];
        #pragma unroll 1
        for (int h = 0; h < 2; h++) {
            const int nl = h * 32 + warp;
            const __half2 hv = neuron_compute<true>(
                stg + nl * DEG, sa, scr, hid_b[m * GSZ + nl]);
            const int node = N_IN + m * GSZ + nl;
            if (node < SMEM_NODES) sa_mut [node * PAIRS] = hv;
            else                   scr_mut[(node - SMEM_NODES) * PAIRS] = hv;
        }

        CP_WAIT0();
        __syncthreads();
        buf ^= 1;
    }

    // ---- Head stage: one int2 per thread (tid < 576) into stage[buf].
    if (tid < HWORDS)
        cp_async8((unsigned int)__cvta_generic_to_shared(&s->stage[buf][tid]),
                  g_pack + NLAY * N_H * DEG + tid);
    CP_COMMIT();
    CP_WAIT0();
    __syncthreads();   // head stage + layer-5 scratch STGs visible

    // ---- output head: 18 neurons (warps 0..17); accurate tanh on outputs.
    if (warp < N_OUT) {
        const int4* pp = (const int4*)(s->stage[buf] + warp * DEG);
        __half2 acc[8];
        #pragma unroll
        for (int k = 0; k < 8; k++) acc[k] = __floats2half2_rn(0.f, 0.f);
        #pragma unroll
        for (int c = 0; c < DEG / 2; c++) {
            const int4 p = pp[c];
            const int q  = ((c >> 1) & 1) * 4;
            const int e0 = (2 * c) & 3;
            #define GATH(II, WW, KK) { const int ii = (II);                           \
                const __half2 v = (ii < SMEM_NODES) ? sa[ii * PAIRS]                  \
                                                    : scr[(ii - SMEM_NODES) * PAIRS]; \
                acc[KK] = __hfma2(v, *(const __half2*)&(WW), acc[KK]); }
            GATH(p.x, p.y, q + e0); GATH(p.z, p.w, q + e0 + 1);
            #undef GATH
        }
        const float bo = out_b[warp];
        float sl = bo, sh = bo;
        #pragma unroll
        for (int k = 0; k < 8; k++) {
            const float2 f = __half22float2(acc[k]);
            sl += f.x; sh += f.y;
        }
        const int r0 = tile * BT + 2 * lane;
        out[(size_t)r0       * N_OUT + warp] = tanhf(sl);
        out[(size_t)(r0 + 1) * N_OUT + warp] = tanhf(sh);
    }
}

extern "C" void kernel_launch(void* const* d_in, const int* in_sizes, int n_in,
                              void* d_out, int out_size)
{
    const float* obs     = (const float*)d_in[0];
    const int*   hid_src = (const int*)  d_in[1];
    const float* hid_w   = (const float*)d_in[2];
    const float* hid_b   = (const float*)d_in[3];
    const int*   out_src = (const int*)  d_in[4];
    const float* out_w   = (const float*)d_in[5];
    const float* out_b   = (const float*)d_in[6];
    float*       out     = (float*)d_out;

    pack_kernel<<<(PACK_N + 255) / 256, 256>>>(hid_src, hid_w, out_src, out_w);

    const size_t smem = sizeof(SMem);  // 231,424 B
    cudaFuncSetAttribute(policy_kernel,
                         cudaFuncAttributeMaxDynamicSharedMemorySize, (int)smem);
    policy_kernel<<<NTILES, NTHREADS, smem>>>(obs, hid_b, out_b, out);
}

// round 15
// speedup vs baseline: 1.4626x; 1.0448x over previous
#include <cuda_runtime.h>
#include <cuda_fp16.h>
#include <stdint.h>
#include <math.h>

#define N_IN   128
#define NLAY   6
#define N_H    320
#define DEG    32
#define N_OUT  18
#define BATCH  8192
#define BT     64              // batch rows per CTA (2 per lane via half2)
#define PAIRS  32              // row-pairs per tile == lanes
#define SMEM_NODES 1680        // nodes resident in shared (rest -> scratch)
#define SCR_NODES  (2048 - SMEM_NODES)   // 368
#define SMEM_OFF_MAX (SMEM_NODES * PAIRS) // 53760: guard threshold on idx*32
#define NTILES (BATCH / BT)    // 128 CTAs, single wave
#define NWARPS 32
#define NTHREADS (NWARPS * 32) // 1024
#define GSZ    64              // neurons per group (2 per warp, sequential)
#define NGROUPS (NLAY * N_H / GSZ)   // 30
#define FASTG  25              // groups 0..24 (layers 0-4): sources < 1408 -> pure smem
#define SWORDS (GSZ * DEG)     // 2048 packed 4B entries per group
#define HWORDS (N_OUT * DEG)   // 576 head entries
#define PACK_N (NLAY * N_H * DEG + HWORDS)   // 62016

// Packed terms: low16 = src_idx*32 (half2-element offset), high16 = fp16 weight.
__device__ __align__(16) unsigned int g_pack[PACK_N];
// Spilled activations (nodes [1680,2048)); guarded gathers read them back.
__device__ __half2 g_scratch[(size_t)NTILES * SCR_NODES * PAIRS];

struct SMem {
    __half2      acts[SMEM_NODES * PAIRS]; // 215,040 B node-major, pair = lane
    unsigned int stage[2][SWORDS];         //  16,384 B double-buffered packed stage
};                                          // 231,424 B total

__device__ __forceinline__ float fast_tanh(float x) {
    float y;
    asm("tanh.approx.f32 %0, %1;" : "=f"(y) : "f"(x));
    return y;
}
__device__ __forceinline__ void cp_async8(unsigned int saddr, const void* g) {
    asm volatile("cp.async.ca.shared.global [%0], [%1], 8;" :: "r"(saddr), "l"(g));
}
__device__ __forceinline__ void cp_async4(unsigned int saddr, const void* g) {
    asm volatile("cp.async.ca.shared.global [%0], [%1], 4;" :: "r"(saddr), "l"(g));
}
#define CP_COMMIT() asm volatile("cp.async.commit_group;" ::: "memory")
#define CP_WAIT0()  asm volatile("cp.async.wait_group 0;"  ::: "memory")

// One neuron: 32 gathers from the 4B-packed stage. Chain mapping == R7:
// term d -> acc[((d/4)&1)*4 + d%4]; sequential fp32 epilogue (R7 numerics).
template<bool GUARD>
__device__ __forceinline__ __half2 neuron_compute(
    const unsigned int* __restrict__ stg_n,   // stage + n_local*DEG
    const __half2* __restrict__ sa, const __half2* __restrict__ scr,
    float bb)
{
    const uint4* pp = (const uint4*)stg_n;    // 8x LDS.128, 4 packed terms each
    __half2 acc[8];
    #pragma unroll
    for (int k = 0; k < 8; k++) acc[k] = __floats2half2_rn(0.f, 0.f);
    #pragma unroll
    for (int c = 0; c < 8; c++) {             // terms 4c .. 4c+3
        const uint4 p = pp[c];
        const int q = (c & 1) * 4;
        #define TERM(PV, K) {                                                       \
            const unsigned int pv = (PV);                                           \
            const int off = (int)(pv & 0xFFFFu);          /* idx*32 */              \
            const unsigned int w2u = __byte_perm(pv, pv, 0x3232); /* (w,w) */       \
            const __half2 v = GUARD ? ((off < SMEM_OFF_MAX) ? sa[off]               \
                                        : scr[off - SMEM_OFF_MAX])                  \
                                    : sa[off];                                      \
            acc[K] = __hfma2(v, *(const __half2*)&w2u, acc[K]); }
        TERM(p.x, q + 0); TERM(p.y, q + 1); TERM(p.z, q + 2); TERM(p.w, q + 3);
        #undef TERM
    }
    float sl = bb, sh = bb;
    #pragma unroll
    for (int k = 0; k < 8; k++) {
        const float2 f = __half22float2(acc[k]);
        sl += f.x; sh += f.y;
    }
    return __floats2half2_rn(fast_tanh(sl), fast_tanh(sh));
}

// Pre-pass: pack (idx*32 | fp16(w)<<16) for hidden layers + head.
__global__ void pack_kernel(const int* __restrict__ hs, const float* __restrict__ hw,
                            const int* __restrict__ os, const float* __restrict__ ow)
{
    const int i = blockIdx.x * 256 + threadIdx.x;
    if (i >= PACK_N) return;
    int idx; float w;
    if (i < NLAY * N_H * DEG) { idx = hs[i]; w = hw[i]; }
    else { const int j = i - NLAY * N_H * DEG; idx = os[j]; w = ow[j]; }
    const __half h = __float2half_rn(w);
    unsigned short hb;
    *(__half*)&hb = h;
    g_pack[i] = (unsigned int)(idx * PAIRS) | ((unsigned int)hb << 16);
}

__global__ void __launch_bounds__(NTHREADS, 1)
policy_kernel(const float* __restrict__ obs,      // [BATCH, N_IN]
              const float* __restrict__ hid_b,    // [NLAY*N_H] flat
              const float* __restrict__ out_b,    // [N_OUT]
              float*       __restrict__ out)      // [BATCH, N_OUT]
{
    extern __shared__ char raw[];
    SMem* s = (SMem*)raw;
    const int tid  = threadIdx.x;
    const int lane = tid & 31;
    const int warp = tid >> 5;
    const int tile = blockIdx.x;

    // ---- obs -> node-major half2 smem. Lane p owns batch rows (2p, 2p+1).
    {
        const int r0 = tile * BT + 2 * lane;
        const float4* o0 = (const float4*)(obs + (size_t)r0 * N_IN);
        const float4* o1 = (const float4*)(obs + (size_t)(r0 + 1) * N_IN);
        const int q = warp;                // 32 warps cover N_IN/4 = 32 quads
        float4 a = o0[q], b = o1[q];
        s->acts[(q * 4 + 0) * PAIRS + lane] = __floats2half2_rn(a.x, b.x);
        s->acts[(q * 4 + 1) * PAIRS + lane] = __floats2half2_rn(a.y, b.y);
        s->acts[(q * 4 + 2) * PAIRS + lane] = __floats2half2_rn(a.z, b.z);
        s->acts[(q * 4 + 3) * PAIRS + lane] = __floats2half2_rn(a.w, b.w);
    }

    const __half2* __restrict__ sa = s->acts + lane;
    __half2* __restrict__ sa_mut   = s->acts + lane;
    __half2* __restrict__ scr_mut  = g_scratch + (size_t)tile * (SCR_NODES * PAIRS) + lane;
    const __half2* __restrict__ scr = scr_mut;

    const unsigned int st0 = (unsigned int)__cvta_generic_to_shared(&s->stage[0][2 * tid]);
    const unsigned int st1 = (unsigned int)__cvta_generic_to_shared(&s->stage[1][2 * tid]);

    // ---- Preload stage for group m=0 into buffer 0 (8 B per thread).
    cp_async8(st0, g_pack + 2 * tid);
    CP_COMMIT();
    CP_WAIT0();
    __syncthreads();   // obs acts + initial stage visible

    int buf = 0;
    // ---- Fast groups (layers 0-4): pure-smem gathers.
    for (int m = 0; m < FASTG; m++) {
        cp_async8(buf ? st0 : st1, g_pack + (size_t)(m + 1) * SWORDS + 2 * tid);
        CP_COMMIT();

        const unsigned int* stg = s->stage[buf];
        #pragma unroll 1
        for (int h = 0; h < 2; h++) {      // 2 neurons per warp, sequential
            const int nl = h * 32 + warp;  // neuron-in-group
            const __half2 hv = neuron_compute<false>(
                stg + nl * DEG, sa, scr, hid_b[m * GSZ + nl]);
            const int node = N_IN + m * GSZ + nl;
            if (node < SMEM_NODES) sa_mut [node * PAIRS] = hv;
            else                   scr_mut[(node - SMEM_NODES) * PAIRS] = hv;
        }

        CP_WAIT0();
        __syncthreads();                   // one barrier per 64 neurons
        buf ^= 1;
    }
    // ---- Guarded groups (layer 5): gathers may hit scratch.
    for (int m = FASTG; m < NGROUPS; m++) {
        if (m + 1 < NGROUPS)
            cp_async8(buf ? st0 : st1, g_pack + (size_t)(m + 1) * SWORDS + 2 * tid);
        CP_COMMIT();

        const unsigned int* stg = s->stage[buf];
        #pragma unroll 1
        for (int h = 0; h < 2; h++) {
            const int nl = h * 32 + warp;
            const __half2 hv = neuron_compute<true>(
                stg + nl * DEG, sa, scr, hid_b[m * GSZ + nl]);
            const int node = N_IN + m * GSZ + nl;
            if (node < SMEM_NODES) sa_mut [node * PAIRS] = hv;
            else                   scr_mut[(node - SMEM_NODES) * PAIRS] = hv;
        }

        CP_WAIT0();
        __syncthreads();
        buf ^= 1;
    }

    // ---- Head stage: one packed word per thread (tid < 576) into stage[buf].
    if (tid < HWORDS)
        cp_async4((unsigned int)__cvta_generic_to_shared(&s->stage[buf][tid]),
                  g_pack + NLAY * N_H * DEG + tid);
    CP_COMMIT();
    CP_WAIT0();
    __syncthreads();   // head stage + layer-5 scratch STGs visible

    // ---- output head: 18 neurons (warps 0..17); accurate tanh on outputs.
    if (warp < N_OUT) {
        const __half2 hv_dummy = neuron_compute<true>(
            s->stage[buf] + warp * DEG, sa, scr, 0.f);
        (void)hv_dummy;  // recompute below with fp32 tanh; see note
        // Accurate-output path (same gathers, accurate tanhf):
        const uint4* pp = (const uint4*)(s->stage[buf] + warp * DEG);
        __half2 acc[8];
        #pragma unroll
        for (int k = 0; k < 8; k++) acc[k] = __floats2half2_rn(0.f, 0.f);
        #pragma unroll
        for (int c = 0; c < 8; c++) {
            const uint4 p = pp[c];
            const int q = (c & 1) * 4;
            #define TERM(PV, K) {                                                   \
                const unsigned int pv = (PV);                                       \
                const int off = (int)(pv & 0xFFFFu);                                \
                const unsigned int w2u = __byte_perm(pv, pv, 0x3232);               \
                const __half2 v = (off < SMEM_OFF_MAX) ? sa[off]                    \
                                                       : scr[off - SMEM_OFF_MAX];  \
                acc[K] = __hfma2(v, *(const __half2*)&w2u, acc[K]); }
            TERM(p.x, q + 0); TERM(p.y, q + 1); TERM(p.z, q + 2); TERM(p.w, q + 3);
            #undef TERM
        }
        const float bo = out_b[warp];
        float sl = bo, sh = bo;
        #pragma unroll
        for (int k = 0; k < 8; k++) {
            const float2 f = __half22float2(acc[k]);
            sl += f.x; sh += f.y;
        }
        const int r0 = tile * BT + 2 * lane;
        out[(size_t)r0       * N_OUT + warp] = tanhf(sl);
        out[(size_t)(r0 + 1) * N_OUT + warp] = tanhf(sh);
    }
}

extern "C" void kernel_launch(void* const* d_in, const int* in_sizes, int n_in,
                              void* d_out, int out_size)
{
    const float* obs     = (const float*)d_in[0];
    const int*   hid_src = (const int*)  d_in[1];
    const float* hid_w   = (const float*)d_in[2];
    const float* hid_b   = (const float*)d_in[3];
    const int*   out_src = (const int*)  d_in[4];
    const float* out_w   = (const float*)d_in[5];
    const float* out_b   = (const float*)d_in[6];
    float*       out     = (float*)d_out;

    pack_kernel<<<(PACK_N + 255) / 256, 256>>>(hid_src, hid_w, out_src, out_w);

    const size_t smem = sizeof(SMem);  // 231,424 B
    cudaFuncSetAttribute(policy_kernel,
                         cudaFuncAttributeMaxDynamicSharedMemorySize, (int)smem);
    policy_kernel<<<NTILES, NTHREADS, smem>>>(obs, hid_b, out_b, out);
}

// round 16
// speedup vs baseline: 1.6036x; 1.0964x over previous
#include <cuda_runtime.h>
#include <cuda_fp16.h>
#include <stdint.h>
#include <math.h>

#define N_IN   128
#define NLAY   6
#define N_H    320
#define DEG    32
#define N_OUT  18
#define BATCH  8192
#define BT     64              // batch rows per CTA (2 per lane via half2)
#define PAIRS  32              // row-pairs per tile == lanes
#define SMEM_NODES 1680        // nodes resident in shared (rest -> scratch)
#define SCR_NODES  (2048 - SMEM_NODES)   // 368
#define SMEM_OFF_MAX (SMEM_NODES * PAIRS) // 53760: guard threshold on idx*32
#define NTILES (BATCH / BT)    // 128 CTAs, single wave
#define NWARPS 32
#define NTHREADS (NWARPS * 32) // 1024
#define GSZ    64              // neurons per group (2 per warp, sequential)
#define NGROUPS (NLAY * N_H / GSZ)   // 30
#define FASTG  25              // groups 0..24 (layers 0-4): sources < 1408 -> pure smem
#define SWORDS (GSZ * DEG)     // 2048 packed 4B entries per group
#define HWORDS (N_OUT * DEG)   // 576 head entries
#define PACK_N (NLAY * N_H * DEG + HWORDS)   // 62016

// Packed terms: low16 = src_idx*32 (half2-element offset), high16 = fp16 weight.
__device__ __align__(16) unsigned int g_pack[PACK_N];
// Spilled activations (nodes [1680,2048)); guarded gathers read them back.
__device__ __half2 g_scratch[(size_t)NTILES * SCR_NODES * PAIRS];

struct SMem {
    __half2      acts[SMEM_NODES * PAIRS]; // 215,040 B node-major, pair = lane
    unsigned int stage[2][SWORDS];         //  16,384 B double-buffered packed stage
};                                          // 231,424 B total

__device__ __forceinline__ float fast_tanh(float x) {
    float y;
    asm("tanh.approx.f32 %0, %1;" : "=f"(y) : "f"(x));
    return y;
}
__device__ __forceinline__ void cp_async8(unsigned int saddr, const void* g) {
    asm volatile("cp.async.ca.shared.global [%0], [%1], 8;" :: "r"(saddr), "l"(g));
}
__device__ __forceinline__ void cp_async4(unsigned int saddr, const void* g) {
    asm volatile("cp.async.ca.shared.global [%0], [%1], 4;" :: "r"(saddr), "l"(g));
}
#define CP_COMMIT() asm volatile("cp.async.commit_group;" ::: "memory")
#define CP_WAIT0()  asm volatile("cp.async.wait_group 0;"  ::: "memory")

// One neuron: 32 gathers from the 4B-packed stage. Chain mapping == R7
// (term d -> acc[((d/4)&1)*4 + d%4]); HADD2 pair-reduce + fp32 finish (R9).
// Weight (w,w) comes from the packed word's high half via __high2half2 —
// ptxas folds this into the HFMA2 .H1_H1 operand selector (no PRMT).
template<bool GUARD>
__device__ __forceinline__ __half2 neuron_compute(
    const unsigned int* __restrict__ stg_n,   // stage + n_local*DEG
    const __half2* __restrict__ sa, const __half2* __restrict__ scr,
    float bb)
{
    const uint4* pp = (const uint4*)stg_n;    // 8x LDS.128, 4 packed terms each
    __half2 acc[8];
    #pragma unroll
    for (int k = 0; k < 8; k++) acc[k] = __floats2half2_rn(0.f, 0.f);
    #pragma unroll
    for (int c = 0; c < 8; c++) {             // terms 4c .. 4c+3
        const uint4 p = pp[c];
        const int q = (c & 1) * 4;
        #define TERM(PV, K) {                                                       \
            const unsigned int pv = (PV);                                           \
            const int off = (int)(pv & 0xFFFFu);          /* idx*32 */              \
            const __half2 w2 = __high2half2(*(const __half2*)&pv); /* .H1_H1 */     \
            const __half2 v = GUARD ? ((off < SMEM_OFF_MAX) ? sa[off]               \
                                        : scr[off - SMEM_OFF_MAX])                  \
                                    : sa[off];                                      \
            acc[K] = __hfma2(v, w2, acc[K]); }
        TERM(p.x, q + 0); TERM(p.y, q + 1); TERM(p.z, q + 2); TERM(p.w, q + 3);
        #undef TERM
    }
    // Epilogue: one fp16 pair-reduction level (R9), then fp32 finish.
    const __half2 r0 = __hadd2(acc[0], acc[1]);
    const __half2 r1 = __hadd2(acc[2], acc[3]);
    const __half2 r2 = __hadd2(acc[4], acc[5]);
    const __half2 r3 = __hadd2(acc[6], acc[7]);
    const float2 f0 = __half22float2(r0);
    const float2 f1 = __half22float2(r1);
    const float2 f2 = __half22float2(r2);
    const float2 f3 = __half22float2(r3);
    const float sl = ((f0.x + f1.x) + (f2.x + f3.x)) + bb;
    const float sh = ((f0.y + f1.y) + (f2.y + f3.y)) + bb;
    return __floats2half2_rn(fast_tanh(sl), fast_tanh(sh));
}

// Pre-pass: pack (idx*32 | fp16(w)<<16) for hidden layers + head.
__global__ void pack_kernel(const int* __restrict__ hs, const float* __restrict__ hw,
                            const int* __restrict__ os, const float* __restrict__ ow)
{
    const int i = blockIdx.x * 256 + threadIdx.x;
    if (i >= PACK_N) return;
    int idx; float w;
    if (i < NLAY * N_H * DEG) { idx = hs[i]; w = hw[i]; }
    else { const int j = i - NLAY * N_H * DEG; idx = os[j]; w = ow[j]; }
    const __half h = __float2half_rn(w);
    unsigned short hb;
    *(__half*)&hb = h;
    g_pack[i] = (unsigned int)(idx * PAIRS) | ((unsigned int)hb << 16);
}

__global__ void __launch_bounds__(NTHREADS, 1)
policy_kernel(const float* __restrict__ obs,      // [BATCH, N_IN]
              const float* __restrict__ hid_b,    // [NLAY*N_H] flat
              const float* __restrict__ out_b,    // [N_OUT]
              float*       __restrict__ out)      // [BATCH, N_OUT]
{
    extern __shared__ char raw[];
    SMem* s = (SMem*)raw;
    const int tid  = threadIdx.x;
    const int lane = tid & 31;
    const int warp = tid >> 5;
    const int tile = blockIdx.x;

    // ---- obs -> node-major half2 smem. Lane p owns batch rows (2p, 2p+1).
    {
        const int r0 = tile * BT + 2 * lane;
        const float4* o0 = (const float4*)(obs + (size_t)r0 * N_IN);
        const float4* o1 = (const float4*)(obs + (size_t)(r0 + 1) * N_IN);
        const int q = warp;                // 32 warps cover N_IN/4 = 32 quads
        float4 a = o0[q], b = o1[q];
        s->acts[(q * 4 + 0) * PAIRS + lane] = __floats2half2_rn(a.x, b.x);
        s->acts[(q * 4 + 1) * PAIRS + lane] = __floats2half2_rn(a.y, b.y);
        s->acts[(q * 4 + 2) * PAIRS + lane] = __floats2half2_rn(a.z, b.z);
        s->acts[(q * 4 + 3) * PAIRS + lane] = __floats2half2_rn(a.w, b.w);
    }

    const __half2* __restrict__ sa = s->acts + lane;
    __half2* __restrict__ sa_mut   = s->acts + lane;
    __half2* __restrict__ scr_mut  = g_scratch + (size_t)tile * (SCR_NODES * PAIRS) + lane;
    const __half2* __restrict__ scr = scr_mut;

    const unsigned int st0 = (unsigned int)__cvta_generic_to_shared(&s->stage[0][2 * tid]);
    const unsigned int st1 = (unsigned int)__cvta_generic_to_shared(&s->stage[1][2 * tid]);

    // ---- Preload stage for group m=0 into buffer 0 (8 B per thread).
    cp_async8(st0, g_pack + 2 * tid);
    CP_COMMIT();
    CP_WAIT0();
    __syncthreads();   // obs acts + initial stage visible

    int buf = 0;
    // ---- Fast groups (layers 0-4): pure-smem gathers.
    for (int m = 0; m < FASTG; m++) {
        cp_async8(buf ? st0 : st1, g_pack + (size_t)(m + 1) * SWORDS + 2 * tid);
        CP_COMMIT();

        const unsigned int* stg = s->stage[buf];
        #pragma unroll 1
        for (int h = 0; h < 2; h++) {      // 2 neurons per warp, sequential
            const int nl = h * 32 + warp;  // neuron-in-group
            const __half2 hv = neuron_compute<false>(
                stg + nl * DEG, sa, scr, hid_b[m * GSZ + nl]);
            const int node = N_IN + m * GSZ + nl;
            if (node < SMEM_NODES) sa_mut [node * PAIRS] = hv;
            else                   scr_mut[(node - SMEM_NODES) * PAIRS] = hv;
        }

        CP_WAIT0();
        __syncthreads();                   // one barrier per 64 neurons
        buf ^= 1;
    }
    // ---- Guarded groups (layer 5): gathers may hit scratch.
    for (int m = FASTG; m < NGROUPS; m++) {
        if (m + 1 < NGROUPS)
            cp_async8(buf ? st0 : st1, g_pack + (size_t)(m + 1) * SWORDS + 2 * tid);
        CP_COMMIT();

        const unsigned int* stg = s->stage[buf];
        #pragma unroll 1
        for (int h = 0; h < 2; h++) {
            const int nl = h * 32 + warp;
            const __half2 hv = neuron_compute<true>(
                stg + nl * DEG, sa, scr, hid_b[m * GSZ + nl]);
            const int node = N_IN + m * GSZ + nl;
            if (node < SMEM_NODES) sa_mut [node * PAIRS] = hv;
            else                   scr_mut[(node - SMEM_NODES) * PAIRS] = hv;
        }

        CP_WAIT0();
        __syncthreads();
        buf ^= 1;
    }

    // ---- Head stage: one packed word per thread (tid < 576) into stage[buf].
    if (tid < HWORDS)
        cp_async4((unsigned int)__cvta_generic_to_shared(&s->stage[buf][tid]),
                  g_pack + NLAY * N_H * DEG + tid);
    CP_COMMIT();
    CP_WAIT0();
    __syncthreads();   // head stage + layer-5 scratch STGs visible

    // ---- output head: 18 neurons (warps 0..17); accurate tanh on outputs.
    if (warp < N_OUT) {
        const uint4* pp = (const uint4*)(s->stage[buf] + warp * DEG);
        __half2 acc[8];
        #pragma unroll
        for (int k = 0; k < 8; k++) acc[k] = __floats2half2_rn(0.f, 0.f);
        #pragma unroll
        for (int c = 0; c < 8; c++) {
            const uint4 p = pp[c];
            const int q = (c & 1) * 4;
            #define TERM(PV, K) {                                                   \
                const unsigned int pv = (PV);                                       \
                const int off = (int)(pv & 0xFFFFu);                                \
                const __half2 w2 = __high2half2(*(const __half2*)&pv);              \
                const __half2 v = (off < SMEM_OFF_MAX) ? sa[off]                    \
                                                       : scr[off - SMEM_OFF_MAX];  \
                acc[K] = __hfma2(v, w2, acc[K]); }
            TERM(p.x, q + 0); TERM(p.y, q + 1); TERM(p.z, q + 2); TERM(p.w, q + 3);
            #undef TERM
        }
        const __half2 r0h = __hadd2(acc[0], acc[1]);
        const __half2 r1h = __hadd2(acc[2], acc[3]);
        const __half2 r2h = __hadd2(acc[4], acc[5]);
        const __half2 r3h = __hadd2(acc[6], acc[7]);
        const float2 f0 = __half22float2(r0h);
        const float2 f1 = __half22float2(r1h);
        const float2 f2 = __half22float2(r2h);
        const float2 f3 = __half22float2(r3h);
        const float bo = out_b[warp];
        const float sl = ((f0.x + f1.x) + (f2.x + f3.x)) + bo;
        const float sh = ((f0.y + f1.y) + (f2.y + f3.y)) + bo;
        const int r0 = tile * BT + 2 * lane;
        out[(size_t)r0       * N_OUT + warp] = tanhf(sl);
        out[(size_t)(r0 + 1) * N_OUT + warp] = tanhf(sh);
    }
}

extern "C" void kernel_launch(void* const* d_in, const int* in_sizes, int n_in,
                              void* d_out, int out_size)
{
    const float* obs     = (const float*)d_in[0];
    const int*   hid_src = (const int*)  d_in[1];
    const float* hid_w   = (const float*)d_in[2];
    const float* hid_b   = (const float*)d_in[3];
    const int*   out_src = (const int*)  d_in[4];
    const float* out_w   = (const float*)d_in[5];
    const float* out_b   = (const float*)d_in[6];
    float*       out     = (float*)d_out;

    pack_kernel<<<(PACK_N + 255) / 256, 256>>>(hid_src, hid_w, out_src, out_w);

    const size_t smem = sizeof(SMem);  // 231,424 B
    cudaFuncSetAttribute(policy_kernel,
                         cudaFuncAttributeMaxDynamicSharedMemorySize, (int)smem);
    policy_kernel<<<NTILES, NTHREADS, smem>>>(obs, hid_b, out_b, out);
}

// round 17
// speedup vs baseline: 1.6927x; 1.0556x over previous
#include <cuda_runtime.h>
#include <cuda_fp16.h>
#include <stdint.h>
#include <math.h>

#define N_IN   128
#define NLAY   6
#define N_H    320
#define DEG    32
#define N_OUT  18
#define BATCH  8192
#define BT     64              // batch rows per CTA (2 per lane via half2)
#define PAIRS  32              // row-pairs per tile == lanes
#define SMEM_NODES 1680        // nodes resident in shared (rest -> scratch)
#define SCR_NODES  (2048 - SMEM_NODES)   // 368
#define SMEM_OFF_MAX (SMEM_NODES * PAIRS) // 53760: guard threshold on idx*32
#define NTILES (BATCH / BT)    // 128 CTAs, single wave
#define NWARPS 32
#define NTHREADS (NWARPS * 32) // 1024
#define GSZ    64              // neurons per group (2 per warp, sequential)
#define NGROUPS (NLAY * N_H / GSZ)   // 30
#define FASTG  25              // groups 0..24 (layers 0-4): sources < 1408 -> pure smem
#define SWORDS (GSZ * DEG)     // 2048 packed 4B term entries per group
#define STWORDS (SWORDS + GSZ) // 2112: terms + 64 packed bias words
#define HWORDS (N_OUT * DEG)   // 576 head entries
#define PACK_N (NLAY * N_H * DEG + HWORDS)   // 62016
#define NBIAS  (NLAY * N_H)    // 1920 hidden biases

// Packed terms: low16 = src_idx*32 (half2-element offset), high16 = fp16 weight.
__device__ __align__(16) unsigned int g_pack[PACK_N];
// Packed hidden biases: half2(b,b) per neuron, as 32-bit words.
__device__ __align__(16) unsigned int g_bias[NBIAS];
// Spilled activations (nodes [1680,2048)); guarded gathers read them back.
__device__ __half2 g_scratch[(size_t)NTILES * SCR_NODES * PAIRS];

struct SMem {
    __half2      acts[SMEM_NODES * PAIRS]; // 215,040 B node-major, pair = lane
    unsigned int stage[2][STWORDS];        //  16,896 B double-buffered stage
};                                          // 231,936 B total (cap 232,448)

__device__ __forceinline__ float fast_tanh(float x) {
    float y;
    asm("tanh.approx.f32 %0, %1;" : "=f"(y) : "f"(x));
    return y;
}
__device__ __forceinline__ void cp_async8(unsigned int saddr, const void* g) {
    asm volatile("cp.async.ca.shared.global [%0], [%1], 8;" :: "r"(saddr), "l"(g));
}
__device__ __forceinline__ void cp_async4(unsigned int saddr, const void* g) {
    asm volatile("cp.async.ca.shared.global [%0], [%1], 4;" :: "r"(saddr), "l"(g));
}
#define CP_COMMIT() asm volatile("cp.async.commit_group;" ::: "memory")
#define CP_WAIT0()  asm volatile("cp.async.wait_group 0;"  ::: "memory")

// One neuron: 32 gathers from the 4B-packed stage. Chain mapping == R7
// (term d -> acc[((d/4)&1)*4 + d%4]). Bias rides in acc[0] (fp16).
// Epilogue: two HADD2 reduction levels, fp32 finish, fast_tanh.
template<bool GUARD>
__device__ __forceinline__ __half2 neuron_compute(
    const unsigned int* __restrict__ stg_n,   // stage + n_local*DEG
    const __half2* __restrict__ sa, const __half2* __restrict__ scr,
    __half2 bias2)
{
    const uint4* pp = (const uint4*)stg_n;    // 8x LDS.128, 4 packed terms each
    __half2 acc[8];
    acc[0] = bias2;
    #pragma unroll
    for (int k = 1; k < 8; k++) acc[k] = __floats2half2_rn(0.f, 0.f);
    #pragma unroll
    for (int c = 0; c < 8; c++) {             // terms 4c .. 4c+3
        const uint4 p = pp[c];
        const int q = (c & 1) * 4;
        #define TERM(PV, K) {                                                       \
            const unsigned int pv = (PV);                                           \
            const int off = (int)(pv & 0xFFFFu);          /* idx*32 */              \
            const __half2 w2 = __high2half2(*(const __half2*)&pv); /* .H1_H1 */     \
            const __half2 v = GUARD ? ((off < SMEM_OFF_MAX) ? sa[off]               \
                                        : scr[off - SMEM_OFF_MAX])                  \
                                    : sa[off];                                      \
            acc[K] = __hfma2(v, w2, acc[K]); }
        TERM(p.x, q + 0); TERM(p.y, q + 1); TERM(p.z, q + 2); TERM(p.w, q + 3);
        #undef TERM
    }
    // Two HADD2 levels, then fp32 finish.
    const __half2 r0 = __hadd2(acc[0], acc[1]);
    const __half2 r1 = __hadd2(acc[2], acc[3]);
    const __half2 r2 = __hadd2(acc[4], acc[5]);
    const __half2 r3 = __hadd2(acc[6], acc[7]);
    const __half2 h0 = __hadd2(r0, r1);
    const __half2 h1 = __hadd2(r2, r3);
    const float2 f0 = __half22float2(h0);
    const float2 f1 = __half22float2(h1);
    const float sl = f0.x + f1.x;
    const float sh = f0.y + f1.y;
    return __floats2half2_rn(fast_tanh(sl), fast_tanh(sh));
}

// Pre-pass: pack terms (idx*32 | fp16(w)<<16) and biases half2(b,b).
__global__ void pack_kernel(const int* __restrict__ hs, const float* __restrict__ hw,
                            const int* __restrict__ os, const float* __restrict__ ow,
                            const float* __restrict__ hb)
{
    const int i = blockIdx.x * 256 + threadIdx.x;
    if (i < PACK_N) {
        int idx; float w;
        if (i < NLAY * N_H * DEG) { idx = hs[i]; w = hw[i]; }
        else { const int j = i - NLAY * N_H * DEG; idx = os[j]; w = ow[j]; }
        const __half h = __float2half_rn(w);
        unsigned short hb16;
        *(__half*)&hb16 = h;
        g_pack[i] = (unsigned int)(idx * PAIRS) | ((unsigned int)hb16 << 16);
    }
    if (i < NBIAS) {
        const __half2 b2 = __float2half2_rn(hb[i]);
        g_bias[i] = *(const unsigned int*)&b2;
    }
}

__global__ void __launch_bounds__(NTHREADS, 1)
policy_kernel(const float* __restrict__ obs,      // [BATCH, N_IN]
              const float* __restrict__ out_b,    // [N_OUT]
              float*       __restrict__ out)      // [BATCH, N_OUT]
{
    extern __shared__ char raw[];
    SMem* s = (SMem*)raw;
    const int tid  = threadIdx.x;
    const int lane = tid & 31;
    const int warp = tid >> 5;
    const int tile = blockIdx.x;

    // ---- obs -> node-major half2 smem. Lane p owns batch rows (2p, 2p+1).
    {
        const int r0 = tile * BT + 2 * lane;
        const float4* o0 = (const float4*)(obs + (size_t)r0 * N_IN);
        const float4* o1 = (const float4*)(obs + (size_t)(r0 + 1) * N_IN);
        const int q = warp;                // 32 warps cover N_IN/4 = 32 quads
        float4 a = o0[q], b = o1[q];
        s->acts[(q * 4 + 0) * PAIRS + lane] = __floats2half2_rn(a.x, b.x);
        s->acts[(q * 4 + 1) * PAIRS + lane] = __floats2half2_rn(a.y, b.y);
        s->acts[(q * 4 + 2) * PAIRS + lane] = __floats2half2_rn(a.z, b.z);
        s->acts[(q * 4 + 3) * PAIRS + lane] = __floats2half2_rn(a.w, b.w);
    }

    const __half2* __restrict__ sa = s->acts + lane;
    __half2* __restrict__ sa_mut   = s->acts + lane;
    __half2* __restrict__ scr_mut  = g_scratch + (size_t)tile * (SCR_NODES * PAIRS) + lane;
    const __half2* __restrict__ scr = scr_mut;

    const unsigned int st0 = (unsigned int)__cvta_generic_to_shared(&s->stage[0][2 * tid]);
    const unsigned int st1 = (unsigned int)__cvta_generic_to_shared(&s->stage[1][2 * tid]);
    const unsigned int sb0 = (unsigned int)__cvta_generic_to_shared(&s->stage[0][SWORDS + tid]);
    const unsigned int sb1 = (unsigned int)__cvta_generic_to_shared(&s->stage[1][SWORDS + tid]);

    // ---- Preload stage for group m=0 into buffer 0 (terms + bias).
    cp_async8(st0, g_pack + 2 * tid);
    if (tid < GSZ) cp_async4(sb0, g_bias + tid);
    CP_COMMIT();
    CP_WAIT0();
    __syncthreads();   // obs acts + initial stage visible

    int buf = 0;
    // ---- Fast groups (layers 0-4): pure-smem gathers.
    for (int m = 0; m < FASTG; m++) {
        cp_async8(buf ? st0 : st1, g_pack + (size_t)(m + 1) * SWORDS + 2 * tid);
        if (tid < GSZ) cp_async4(buf ? sb0 : sb1, g_bias + (m + 1) * GSZ + tid);
        CP_COMMIT();

        const unsigned int* stg = s->stage[buf];
        #pragma unroll 1
        for (int h = 0; h < 2; h++) {      // 2 neurons per warp, sequential
            const int nl = h * 32 + warp;  // neuron-in-group
            const __half2 b2 = *(const __half2*)&stg[SWORDS + nl];  // LDS.32 bcast
            const __half2 hv = neuron_compute<false>(stg + nl * DEG, sa, scr, b2);
            const int node = N_IN + m * GSZ + nl;
            if (node < SMEM_NODES) sa_mut [node * PAIRS] = hv;
            else                   scr_mut[(node - SMEM_NODES) * PAIRS] = hv;
        }

        CP_WAIT0();
        __syncthreads();                   // one barrier per 64 neurons
        buf ^= 1;
    }
    // ---- Guarded groups (layer 5): gathers may hit scratch.
    for (int m = FASTG; m < NGROUPS; m++) {
        if (m + 1 < NGROUPS) {
            cp_async8(buf ? st0 : st1, g_pack + (size_t)(m + 1) * SWORDS + 2 * tid);
            if (tid < GSZ) cp_async4(buf ? sb0 : sb1, g_bias + (m + 1) * GSZ + tid);
        }
        CP_COMMIT();

        const unsigned int* stg = s->stage[buf];
        #pragma unroll 1
        for (int h = 0; h < 2; h++) {
            const int nl = h * 32 + warp;
            const __half2 b2 = *(const __half2*)&stg[SWORDS + nl];
            const __half2 hv = neuron_compute<true>(stg + nl * DEG, sa, scr, b2);
            const int node = N_IN + m * GSZ + nl;
            if (node < SMEM_NODES) sa_mut [node * PAIRS] = hv;
            else                   scr_mut[(node - SMEM_NODES) * PAIRS] = hv;
        }

        CP_WAIT0();
        __syncthreads();
        buf ^= 1;
    }

    // ---- Head stage: one packed word per thread (tid < 576) into stage[buf].
    if (tid < HWORDS)
        cp_async4((unsigned int)__cvta_generic_to_shared(&s->stage[buf][tid]),
                  g_pack + NLAY * N_H * DEG + tid);
    CP_COMMIT();
    CP_WAIT0();
    __syncthreads();   // head stage + layer-5 scratch STGs visible

    // ---- output head: 18 neurons (warps 0..17); fp32 bias + accurate tanh.
    if (warp < N_OUT) {
        const uint4* pp = (const uint4*)(s->stage[buf] + warp * DEG);
        __half2 acc[8];
        #pragma unroll
        for (int k = 0; k < 8; k++) acc[k] = __floats2half2_rn(0.f, 0.f);
        #pragma unroll
        for (int c = 0; c < 8; c++) {
            const uint4 p = pp[c];
            const int q = (c & 1) * 4;
            #define TERM(PV, K) {                                                   \
                const unsigned int pv = (PV);                                       \
                const int off = (int)(pv & 0xFFFFu);                                \
                const __half2 w2 = __high2half2(*(const __half2*)&pv);              \
                const __half2 v = (off < SMEM_OFF_MAX) ? sa[off]                    \
                                                       : scr[off - SMEM_OFF_MAX];  \
                acc[K] = __hfma2(v, w2, acc[K]); }
            TERM(p.x, q + 0); TERM(p.y, q + 1); TERM(p.z, q + 2); TERM(p.w, q + 3);
            #undef TERM
        }
        const __half2 r0h = __hadd2(acc[0], acc[1]);
        const __half2 r1h = __hadd2(acc[2], acc[3]);
        const __half2 r2h = __hadd2(acc[4], acc[5]);
        const __half2 r3h = __hadd2(acc[6], acc[7]);
        const float2 f0 = __half22float2(r0h);
        const float2 f1 = __half22float2(r1h);
        const float2 f2 = __half22float2(r2h);
        const float2 f3 = __half22float2(r3h);
        const float bo = out_b[warp];
        const float sl = ((f0.x + f1.x) + (f2.x + f3.x)) + bo;
        const float sh = ((f0.y + f1.y) + (f2.y + f3.y)) + bo;
        const int r0 = tile * BT + 2 * lane;
        out[(size_t)r0       * N_OUT + warp] = tanhf(sl);
        out[(size_t)(r0 + 1) * N_OUT + warp] = tanhf(sh);
    }
}

extern "C" void kernel_launch(void* const* d_in, const int* in_sizes, int n_in,
                              void* d_out, int out_size)
{
    const float* obs     = (const float*)d_in[0];
    const int*   hid_src = (const int*)  d_in[1];
    const float* hid_w   = (const float*)d_in[2];
    const float* hid_b   = (const float*)d_in[3];
    const int*   out_src = (const int*)  d_in[4];
    const float* out_w   = (const float*)d_in[5];
    const float* out_b   = (const float*)d_in[6];
    float*       out     = (float*)d_out;

    pack_kernel<<<(PACK_N + 255) / 256, 256>>>(hid_src, hid_w, out_src, out_w, hid_b);

    const size_t smem = sizeof(SMem);  // 231,936 B
    cudaFuncSetAttribute(policy_kernel,
                         cudaFuncAttributeMaxDynamicSharedMemorySize, (int)smem);
    policy_kernel<<<NTILES, NTHREADS, smem>>>(obs, out_b, out);
}